// round 15
// baseline (speedup 1.0000x reference)
#include <cuda_runtime.h>

#define NN    8192
#define MAXO  300
#define NW    (NN/64)     // 128 u64 words per mask row
#define CH    2048        // chunk size for chunk_sort
#define CT    512         // chunk_sort threads (EPB 4)
#define MT    1024        // merge threads (EPB 8)

typedef unsigned long long u64;

// Static device scratch (no allocation). Fully rewritten every launch.
__device__ u64    g_keys[NN];
__device__ float4 g_boxes[NN];
__device__ float  g_area[NN];
__device__ int    g_sidx[NN];
__device__ __align__(16) u64 g_mask[(size_t)NN * NW];   // 8MB triangle mask

__device__ __forceinline__ void cmpex(u64& a, u64& b, bool up) {
  u64 x = a, y = b;
  if ((x > y) == up) { a = y; b = x; }
}

// ---------------------------------------------------------------------------
// Kernel A1: chunk bitonic sort (unchanged, proven at ~7us).
// ---------------------------------------------------------------------------
__global__ __launch_bounds__(CT, 1)
void chunk_sort(const float* __restrict__ scores) {
  __shared__ u64 sk[CH];
  const int tid   = threadIdx.x;
  const int cbase = blockIdx.x * CH;
  for (int p = tid; p < CH; p += CT) {
    unsigned sb = __float_as_uint(scores[cbase + p]);  // scores>=0: bits monotone
    sk[p] = (((u64)(~sb)) << 32) | (unsigned)(cbase + p);
  }
  __syncthreads();
  const int lbase = tid * 4;
  const int gbase = cbase + lbase;
  u64 v[4];
#pragma unroll
  for (int e = 0; e < 4; e++) v[e] = sk[lbase + e];

  cmpex(v[0], v[1], true);
  cmpex(v[2], v[3], false);
  {
    bool up = ((gbase & 4) == 0);
    cmpex(v[0], v[2], up); cmpex(v[1], v[3], up);
    cmpex(v[0], v[1], up); cmpex(v[2], v[3], up);
  }

  for (int k = 8; k <= CH; k <<= 1) {
    const bool up = ((gbase & k) == 0);
    int jj = k >> 1;
    if (jj >= 128) {
#pragma unroll
      for (int e = 0; e < 4; e++) sk[lbase + e] = v[e];
      __syncthreads();
      for (; jj >= 128; jj >>= 1) {
        for (int pp = tid; pp < CH / 2; pp += CT) {
          int p = ((pp & ~(jj - 1)) << 1) | (pp & (jj - 1));
          int q = p | jj;
          bool u2 = (((cbase + p) & k) == 0);
          u64 a = sk[p], b = sk[q];
          if ((a > b) == u2) { sk[p] = b; sk[q] = a; }
        }
        __syncthreads();
      }
#pragma unroll
      for (int e = 0; e < 4; e++) v[e] = sk[lbase + e];
    }
    for (; jj >= 4; jj >>= 1) {
      int s = jj >> 2;
      bool takemin = (((tid & s) == 0) == up);
#pragma unroll
      for (int e = 0; e < 4; e++) {
        u64 o  = __shfl_xor_sync(0xFFFFFFFFu, v[e], s);
        u64 mn = (v[e] < o) ? v[e] : o;
        u64 mx = (v[e] < o) ? o : v[e];
        v[e] = takemin ? mn : mx;
      }
    }
    cmpex(v[0], v[2], up); cmpex(v[1], v[3], up);
    cmpex(v[0], v[1], up); cmpex(v[2], v[3], up);
  }
#pragma unroll
  for (int e = 0; e < 4; e++) g_keys[gbase + e] = v[e];
}

// ---------------------------------------------------------------------------
// Kernel A2: bitonic merge phases k=4096, 8192 (unchanged); emits sorted
// boxes/areas/sidx to globals and inits out to -1.
// ---------------------------------------------------------------------------
__global__ __launch_bounds__(MT, 1)
void merge_kernel(const float4* __restrict__ rois, float* __restrict__ out) {
  extern __shared__ u64 sk[];   // 64KB
  const int tid  = threadIdx.x;
  const int base = tid * 8;
  if (tid < MAXO) out[tid] = -1.0f;
  u64 v[8];
#pragma unroll
  for (int e = 0; e < 8; e++) v[e] = g_keys[base + e];

  for (int k = 2 * CH; k <= NN; k <<= 1) {
    const bool up = ((base & k) == 0);
    int jj = k >> 1;
#pragma unroll
    for (int e = 0; e < 8; e++) sk[base + e] = v[e];
    __syncthreads();
    for (; jj >= 256; jj >>= 1) {
      for (int pp = tid; pp < NN / 2; pp += MT) {
        int p = ((pp & ~(jj - 1)) << 1) | (pp & (jj - 1));
        int q = p | jj;
        bool u2 = ((p & k) == 0);
        u64 a = sk[p], b = sk[q];
        if ((a > b) == u2) { sk[p] = b; sk[q] = a; }
      }
      __syncthreads();
    }
#pragma unroll
    for (int e = 0; e < 8; e++) v[e] = sk[base + e];
    for (; jj >= 8; jj >>= 1) {
      int s = jj >> 3;
      bool takemin = (((tid & s) == 0) == up);
#pragma unroll
      for (int e = 0; e < 8; e++) {
        u64 o  = __shfl_xor_sync(0xFFFFFFFFu, v[e], s);
        u64 mn = (v[e] < o) ? v[e] : o;
        u64 mx = (v[e] < o) ? o : v[e];
        v[e] = takemin ? mn : mx;
      }
    }
#pragma unroll
    for (int j2 = 4; j2; j2 >>= 1)
#pragma unroll
      for (int e = 0; e < 8; e++) { int e2 = e ^ j2; if (e2 > e) cmpex(v[e], v[e2], up); }
  }

#pragma unroll
  for (int e = 0; e < 8; e++) {
    int p  = base + e;
    int id = (int)(unsigned)(v[e] & 0xFFFFFFFFull);
    g_sidx[p] = id;
    float4 bb = rois[id];
    g_boxes[p] = bb;
    g_area[p] = __fmul_rn(__fsub_rn(bb.z, bb.x), __fsub_rn(bb.w, bb.y));
  }
}

// ---------------------------------------------------------------------------
// Kernel B: triangle suppression bitmask v2 — 2 rows per thread to amortize
// the column-box LDS. Block (cb, rg): 256 threads cover rows
// [rg*512, rg*512+512); thread t handles i = rg*512 + {t, t+256}, word cb.
// Bit e set <=> j = cb*64+e >= i AND IoU(i,j) > 0.5 (diag self-bit set).
// ---------------------------------------------------------------------------
__global__ __launch_bounds__(256, 8)
void mask_kernel() {
  const int cb = blockIdx.x;
  const int rg = blockIdx.y;
  const int t  = threadIdx.x;
  const int jbase = cb * 64;
  const int i0 = rg * 512 + t;
  const int i1 = i0 + 256;

  if (jbase + 63 < rg * 512) {          // whole block below diagonal
    g_mask[(size_t)i0 * NW + cb] = 0ull;
    g_mask[(size_t)i1 * NW + cb] = 0ull;
    return;
  }

  __shared__ float4 cbox[64];
  __shared__ float  carea[64];
  if (t < 64) { cbox[t] = g_boxes[jbase + t]; carea[t] = g_area[jbase + t]; }
  __syncthreads();

  const float4 b0 = g_boxes[i0]; const float a0 = g_area[i0];
  const float4 b1 = g_boxes[i1]; const float a1 = g_area[i1];
  u64 bits0 = 0, bits1 = 0;
#pragma unroll 4
  for (int e = 0; e < 64; e++) {
    const float4 bj = cbox[e];
    const float  aj = carea[e];
    {
      float lx = fmaxf(b0.x, bj.x), ly = fmaxf(b0.y, bj.y);
      float rx = fminf(b0.z, bj.z), ry = fminf(b0.w, bj.w);
      float ww = fmaxf(__fsub_rn(rx, lx), 0.0f);
      float hh = fmaxf(__fsub_rn(ry, ly), 0.0f);
      float inter = __fmul_rn(ww, hh);
      float uni   = __fsub_rn(__fadd_rn(a0, aj), inter);
      float d   = __fmaf_rn(-0.5f, uni, inter);
      float tol = 1e-6f * uni;
      bool sup;
      if (d > tol)       sup = true;
      else if (d < -tol) sup = false;
      else               sup = (__fdiv_rn(inter, uni) > 0.5f);
      bits0 |= ((u64)sup) << e;
    }
    {
      float lx = fmaxf(b1.x, bj.x), ly = fmaxf(b1.y, bj.y);
      float rx = fminf(b1.z, bj.z), ry = fminf(b1.w, bj.w);
      float ww = fmaxf(__fsub_rn(rx, lx), 0.0f);
      float hh = fmaxf(__fsub_rn(ry, ly), 0.0f);
      float inter = __fmul_rn(ww, hh);
      float uni   = __fsub_rn(__fadd_rn(a1, aj), inter);
      float d   = __fmaf_rn(-0.5f, uni, inter);
      float tol = 1e-6f * uni;
      bool sup;
      if (d > tol)       sup = true;
      else if (d < -tol) sup = false;
      else               sup = (__fdiv_rn(inter, uni) > 0.5f);
      bits1 |= ((u64)sup) << e;
    }
  }
  if (i0 > jbase + 63)      bits0 = 0ull;
  else if (i0 > jbase)      bits0 &= (~0ull) << (i0 - jbase);
  if (i1 > jbase + 63)      bits1 = 0ull;
  else if (i1 > jbase)      bits1 &= (~0ull) << (i1 - jbase);
  g_mask[(size_t)i0 * NW + cb] = bits0;
  g_mask[(size_t)i1 * NW + cb] = bits1;
}

// ---------------------------------------------------------------------------
// Kernel C: single-warp batched resolver, bit-exact serial greedy.
// rem in registers (lane l owns positions [256l, 256l+256) as R0..R3).
// Per round: extract the 32 lowest FREE positions (no cursor needed: every
// extracted position gets marked — kept via diag self-bit, suppressed via
// its suppressor's row), cp.async their mask rows into smem (MLP=32),
// gather per-lane suppression word Sl (triangle mask => S lower-triangular),
// ballot-resolve, OR kept rows into rem, emit. ~12 rounds total.
// ---------------------------------------------------------------------------
__global__ void resolve_kernel(float* __restrict__ out) {
  __shared__ __align__(16) u64 ring[32][NW];   // 32KB
  __shared__ int cand_s[32];
  const int lane = threadIdx.x;
  const unsigned FULL = 0xFFFFFFFFu;
  u64 R0 = 0, R1 = 0, R2 = 0, R3 = 0;
  int K = 0;

  for (;;) {
    // ---- extract up to 32 lowest free positions ----
    u64 F0 = ~R0, F1 = ~R1, F2 = ~R2, F3 = ~R3;
    int cnt = __popcll(F0) + __popcll(F1) + __popcll(F2) + __popcll(F3);
    int x = cnt;
#pragma unroll
    for (int o = 1; o < 32; o <<= 1) {
      int y = __shfl_up_sync(FULL, x, o);
      if (lane >= o) x += y;
    }
    int total = __shfl_sync(FULL, x, 31);
    int rank  = x - cnt;
    cand_s[lane] = NN;
    __syncwarp();
#pragma unroll
    for (int q = 0; q < 4; q++) {
      u64 f = (q == 0) ? F0 : (q == 1) ? F1 : (q == 2) ? F2 : F3;
      while (f && rank < 32) {
        int b = __ffsll((long long)f) - 1;
        cand_s[rank++] = lane * 256 + q * 64 + b;
        f &= f - 1;
      }
    }
    __syncwarp();
    const int n = (total < 32) ? total : 32;
    if (n == 0) break;
    const int c_l = cand_s[lane];
    const bool valid = (c_l < NN);

    // ---- cp.async the n candidate rows (lane copies its own 32B slice) ----
    for (int m = 0; m < n; m++) {
      int cm = cand_s[m];
      unsigned long long ga;
      asm("cvta.to.global.u64 %0, %1;" : "=l"(ga)
          : "l"((const void*)((const char*)(g_mask + (size_t)cm * NW) + lane * 32)));
      unsigned sa;
      asm("{ .reg .u64 t; cvta.to.shared.u64 t, %1; cvt.u32.u64 %0, t; }" : "=r"(sa)
          : "l"((const void*)((const char*)(&ring[m][0]) + lane * 32)));
      asm volatile("cp.async.cg.shared.global [%0], [%1], 16;\n\t"
                   "cp.async.cg.shared.global [%2], [%3], 16;\n\t"
                   :: "r"(sa), "l"(ga), "r"(sa + 16), "l"(ga + 16) : "memory");
    }
    asm volatile("cp.async.commit_group;\n\tcp.async.wait_group 0;" ::: "memory");
    __syncwarp();

    // ---- gather Sl: bit m = "candidate m suppresses my candidate" ----
    unsigned Sl = 0;
    {
      const int wi = valid ? (c_l >> 6) : 0;
      const int bi = c_l & 63;
      for (int m = 0; m < n; m++)
        Sl |= ((unsigned)((ring[m][wi] >> bi) & 1ull)) << m;
    }

    // ---- exact ballot resolution (S lower-triangular by construction) ----
    unsigned rest = __ballot_sync(FULL, valid);
    unsigned kept = 0;
    while (rest) {
      int m = __ffs(rest) - 1;
      kept |= 1u << m;
      unsigned supm = __ballot_sync(FULL, (Sl >> m) & 1u);
      rest &= ~(supm | (1u << m));
    }

    // ---- emit ----
    if ((kept >> lane) & 1u) {
      int slot = K + __popc(kept & ((1u << lane) - 1u));
      if (slot < MAXO) out[slot] = (float)g_sidx[c_l];
    }
    K += __popc(kept);

    // ---- OR kept rows into rem ----
    unsigned mm = kept;
    while (mm) {
      int m = __ffs(mm) - 1;
      mm &= mm - 1;
      const ulonglong2* rp = reinterpret_cast<const ulonglong2*>(&ring[m][0]) + 2 * lane;
      ulonglong2 a = rp[0], b = rp[1];
      R0 |= a.x; R1 |= a.y; R2 |= b.x; R3 |= b.y;
    }
    if (K >= MAXO) break;
  }
}

// ---------------------------------------------------------------------------
extern "C" void kernel_launch(void* const* d_in, const int* in_sizes, int n_in,
                              void* d_out, int out_size) {
  const void* a0 = d_in[0];
  const void* a1 = d_in[1];
  const float4* rois;
  const float*  scores;
  if (in_sizes[0] >= in_sizes[1]) { rois = (const float4*)a0; scores = (const float*)a1; }
  else                            { rois = (const float4*)a1; scores = (const float*)a0; }

  const int merge_smem = NN * (int)sizeof(u64);                 // 64KB
  cudaFuncSetAttribute(merge_kernel, cudaFuncAttributeMaxDynamicSharedMemorySize,
                       merge_smem);

  chunk_sort<<<NN / CH, CT>>>(scores);
  merge_kernel<<<1, MT, merge_smem>>>(rois, (float*)d_out);
  mask_kernel<<<dim3(NW, NN / 512), 256>>>();
  resolve_kernel<<<1, 32>>>((float*)d_out);
}

// round 16
// speedup vs baseline: 2.1065x; 2.1065x over previous
#include <cuda_runtime.h>

#define NN    8192
#define MAXO  300
#define CH    2048        // chunk size for chunk_sort
#define CT    512         // chunk_sort threads (EPB 4)
#define MT    1024        // fused kernel threads (merge EPB 8)

typedef unsigned long long u64;

// Static device scratch (no allocation). Fully rewritten every launch.
__device__ u64 g_keys[NN];

__device__ __forceinline__ void cmpex(u64& a, u64& b, bool up) {
  u64 x = a, y = b;
  if ((x > y) == up) { a = y; b = x; }
}

// exact decision: IoU(i,j) > 0.5 with IEEE divide semantics
__device__ __forceinline__ bool iou_gt(float4 bi, float ai, float4 bj, float aj) {
  float lx = fmaxf(bi.x, bj.x);
  float ly = fmaxf(bi.y, bj.y);
  float rx = fminf(bi.z, bj.z);
  float ry = fminf(bi.w, bj.w);
  float w  = fmaxf(__fsub_rn(rx, lx), 0.0f);
  float h  = fmaxf(__fsub_rn(ry, ly), 0.0f);
  float inter = __fmul_rn(w, h);
  float uni   = __fsub_rn(__fadd_rn(ai, aj), inter);
  float d   = __fmaf_rn(-0.5f, uni, inter);
  float tol = 1e-6f * uni;
  bool sup = d > tol;
  if (fabsf(d) <= tol) sup = (__fdiv_rn(inter, uni) > 0.5f);   // rare borderline
  return sup;
}

// ---------------------------------------------------------------------------
// Kernel A: chunk bitonic sort (unchanged, proven ~7us). 4 blocks x 512
// threads (EPB 4), each sorts a 2048-chunk with global phases k<=2048.
// ---------------------------------------------------------------------------
__global__ __launch_bounds__(CT, 1)
void chunk_sort(const float* __restrict__ scores) {
  __shared__ u64 sk[CH];
  const int tid   = threadIdx.x;
  const int cbase = blockIdx.x * CH;
  for (int p = tid; p < CH; p += CT) {
    unsigned sb = __float_as_uint(scores[cbase + p]);  // scores>=0: bits monotone
    sk[p] = (((u64)(~sb)) << 32) | (unsigned)(cbase + p);
  }
  __syncthreads();
  const int lbase = tid * 4;
  const int gbase = cbase + lbase;
  u64 v[4];
#pragma unroll
  for (int e = 0; e < 4; e++) v[e] = sk[lbase + e];

  cmpex(v[0], v[1], true);
  cmpex(v[2], v[3], false);
  {
    bool up = ((gbase & 4) == 0);
    cmpex(v[0], v[2], up); cmpex(v[1], v[3], up);
    cmpex(v[0], v[1], up); cmpex(v[2], v[3], up);
  }

  for (int k = 8; k <= CH; k <<= 1) {
    const bool up = ((gbase & k) == 0);
    int jj = k >> 1;
    if (jj >= 128) {
#pragma unroll
      for (int e = 0; e < 4; e++) sk[lbase + e] = v[e];
      __syncthreads();
      for (; jj >= 128; jj >>= 1) {
        for (int pp = tid; pp < CH / 2; pp += CT) {
          int p = ((pp & ~(jj - 1)) << 1) | (pp & (jj - 1));
          int q = p | jj;
          bool u2 = (((cbase + p) & k) == 0);
          u64 a = sk[p], b = sk[q];
          if ((a > b) == u2) { sk[p] = b; sk[q] = a; }
        }
        __syncthreads();
      }
#pragma unroll
      for (int e = 0; e < 4; e++) v[e] = sk[lbase + e];
    }
    for (; jj >= 4; jj >>= 1) {
      int s = jj >> 2;
      bool takemin = (((tid & s) == 0) == up);
#pragma unroll
      for (int e = 0; e < 4; e++) {
        u64 o  = __shfl_xor_sync(0xFFFFFFFFu, v[e], s);
        u64 mn = (v[e] < o) ? v[e] : o;
        u64 mx = (v[e] < o) ? o : v[e];
        v[e] = takemin ? mn : mx;
      }
    }
    cmpex(v[0], v[2], up); cmpex(v[1], v[3], up);
    cmpex(v[0], v[1], up); cmpex(v[2], v[3], up);
  }
#pragma unroll
  for (int e = 0; e < 4; e++) g_keys[gbase + e] = v[e];
}

// ---------------------------------------------------------------------------
// Kernel B (FUSED): bitonic merge (k=4096, 8192) + kept-list greedy with
// EARLY-EXIT vs-kept. Sorted boxes/areas/sidx in shared (192KB dynamic;
// merge key workspace aliases boxes region, dead by then).
// Greedy per batch of 32 candidates:
//   - warp w owns candidate w; lanes stride the kept list, __any_sync exit
//     on first hit (suppressed candidates exit in ~2 iters).
//   - Sball[w] via symmetric-IoU ballot (lane computes iou(cand_lane,cand_w))
//   - warp 0: ballot resolution + append (2 barriers/batch).
// Decision function identical to R12 -> bit-exact serial-greedy keeps.
// ---------------------------------------------------------------------------
__global__ __launch_bounds__(MT, 1)
void mg_kernel(const float4* __restrict__ rois, float* __restrict__ out) {
  extern __shared__ unsigned char blob[];
  u64*    sk     = reinterpret_cast<u64*>(blob);                  // [0,64K)
  float4* sboxes = reinterpret_cast<float4*>(blob);               // [0,128K)
  float*  sarea  = reinterpret_cast<float*>(blob + 131072);       // [128K,160K)
  int*    ssidx  = reinterpret_cast<int*>(blob + 163840);         // [160K,192K)

  __shared__ float4        kb[MAXO + 32];
  __shared__ float         ka[MAXO + 32];
  __shared__ unsigned char supw[32];
  __shared__ unsigned      Sball[32];
  __shared__ int           Ksh;

  const int tid  = threadIdx.x;
  const int w    = tid >> 5;
  const int lane = tid & 31;
  const int base = tid * 8;
  const unsigned FULL = 0xFFFFFFFFu;

  if (tid < MAXO) out[tid] = -1.0f;

  // ---- merge phases k = 4096, 8192 (unchanged from R12) ----
  u64 v[8];
#pragma unroll
  for (int e = 0; e < 8; e++) v[e] = g_keys[base + e];

  for (int k = 2 * CH; k <= NN; k <<= 1) {
    const bool up = ((base & k) == 0);
    int jj = k >> 1;
#pragma unroll
    for (int e = 0; e < 8; e++) sk[base + e] = v[e];
    __syncthreads();
    for (; jj >= 256; jj >>= 1) {
      for (int pp = tid; pp < NN / 2; pp += MT) {
        int p = ((pp & ~(jj - 1)) << 1) | (pp & (jj - 1));
        int q = p | jj;
        bool u2 = ((p & k) == 0);
        u64 a = sk[p], b = sk[q];
        if ((a > b) == u2) { sk[p] = b; sk[q] = a; }
      }
      __syncthreads();
    }
#pragma unroll
    for (int e = 0; e < 8; e++) v[e] = sk[base + e];
    for (; jj >= 8; jj >>= 1) {
      int s = jj >> 3;
      bool takemin = (((tid & s) == 0) == up);
#pragma unroll
      for (int e = 0; e < 8; e++) {
        u64 o  = __shfl_xor_sync(FULL, v[e], s);
        u64 mn = (v[e] < o) ? v[e] : o;
        u64 mx = (v[e] < o) ? o : v[e];
        v[e] = takemin ? mn : mx;
      }
    }
#pragma unroll
    for (int j2 = 4; j2; j2 >>= 1)
#pragma unroll
      for (int e = 0; e < 8; e++) { int e2 = e ^ j2; if (e2 > e) cmpex(v[e], v[e2], up); }
  }
  __syncthreads();   // all sk reads done before aliasing overwrite

  // ---- emit sorted data into shared ----
#pragma unroll
  for (int e = 0; e < 8; e++) {
    int p  = base + e;
    int id = (int)(unsigned)(v[e] & 0xFFFFFFFFull);
    float4 bb = rois[id];
    sboxes[p] = bb;
    sarea[p]  = __fmul_rn(__fsub_rn(bb.z, bb.x), __fsub_rn(bb.w, bb.y));
    ssidx[p]  = id;
  }
  __syncthreads();

  // ---- kept-list greedy with early-exit vs-kept ----
  int K = 0;
  for (int p = 0; p < NN && K < MAXO; p += 32) {
    const float4 bc = sboxes[p + w];      // my warp's candidate (uniform)
    const float  ac = sarea[p + w];

    // vs-kept: lanes stride the kept list; exit on first hit
    bool hit = false;
    for (int k0 = 0; k0 < K; k0 += 32) {
      int k = k0 + lane;
      bool h = (k < K) && iou_gt(bc, ac, kb[k], ka[k]);
      if (__any_sync(FULL, h)) { hit = true; break; }
    }
    // intra-batch matrix row w: bit lane = "cand w suppresses cand lane"
    // (IoU symmetric; computed as iou(cand_lane, cand_w))
    unsigned rb = __ballot_sync(FULL, iou_gt(sboxes[p + lane], sarea[p + lane], bc, ac));
    if (lane == 0) { supw[w] = hit ? 1 : 0; Sball[w] = rb; }
    __syncthreads();

    if (w == 0) {
      unsigned so = __ballot_sync(FULL, supw[lane] != 0);
      unsigned kept = 0;
      if (lane == 0) {
        unsigned rest = ~so;
        while (rest) {
          int m = __ffs(rest) - 1;
          kept |= 1u << m;
          rest &= ~(Sball[m] | (1u << m));   // extra low bits harmless
        }
      }
      kept = __shfl_sync(FULL, kept, 0);
      if ((kept >> lane) & 1u) {
        int slot = K + __popc(kept & ((1u << lane) - 1u));
        kb[slot] = sboxes[p + lane];
        ka[slot] = sarea[p + lane];
        if (slot < MAXO) out[slot] = (float)ssidx[p + lane];
      }
      if (lane == 0) Ksh = K + __popc(kept);
    }
    __syncthreads();
    K = Ksh;
  }
}

// ---------------------------------------------------------------------------
extern "C" void kernel_launch(void* const* d_in, const int* in_sizes, int n_in,
                              void* d_out, int out_size) {
  const void* a0 = d_in[0];
  const void* a1 = d_in[1];
  const float4* rois;
  const float*  scores;
  if (in_sizes[0] >= in_sizes[1]) { rois = (const float4*)a0; scores = (const float*)a1; }
  else                            { rois = (const float4*)a1; scores = (const float*)a0; }

  const int mg_smem = 196608;   // 192KB: boxes(128K) + area(32K) + sidx(32K)
  cudaFuncSetAttribute(mg_kernel, cudaFuncAttributeMaxDynamicSharedMemorySize,
                       mg_smem);

  chunk_sort<<<NN / CH, CT>>>(scores);
  mg_kernel<<<1, MT, mg_smem>>>(rois, (float*)d_out);
}